// round 3
// baseline (speedup 1.0000x reference)
#include <cuda_runtime.h>
#include <cstdint>

#define B_    64
#define T_    2048
#define DIN   256
#define DH    256
#define DC    256
#define DOUT  256
#define G3    768   // 3 gates * 256

// Scratch (allocation-free rule: __device__ globals)
__device__ float g_Gx[(size_t)B_ * T_ * G3];  // x-part gate preactivations (+bias)
__device__ float g_H [(size_t)B_ * T_ * DH];  // h_t for all t (for output GEMM)

// ---------------- helpers ----------------

__device__ __forceinline__ float2 ffma2(float2 a, float2 b, float2 c) {
    union U { float2 f; unsigned long long u; };
    U ua, ub, uc, ud;
    ua.f = a; ub.f = b; uc.f = c;
    asm("fma.rn.f32x2 %0, %1, %2, %3;"
        : "=l"(ud.u) : "l"(ua.u), "l"(ub.u), "l"(uc.u));
    return ud.f;
}

__device__ __forceinline__ uint32_t smem_u32(const void* p) {
    uint32_t a;
    asm("{ .reg .u64 t; cvta.to.shared.u64 t, %1; cvt.u32.u64 %0, t; }"
        : "=r"(a) : "l"(p));
    return a;
}

__device__ __forceinline__ void st_cluster_f32(uint32_t laddr, uint32_t rank, float v) {
    asm volatile("{ .reg .b32 ra; mapa.shared::cluster.u32 ra, %0, %1; "
                 "st.shared::cluster.f32 [ra], %2; }"
                 :: "r"(laddr), "r"(rank), "f"(v) : "memory");
}

__device__ __forceinline__ void cluster_sync_() {
    asm volatile("barrier.cluster.arrive.aligned;" ::: "memory");
    asm volatile("barrier.cluster.wait.aligned;" ::: "memory");
}

__device__ __forceinline__ float sigmoidf_(float x) {
    return 1.0f / (1.0f + __expf(-x));
}

// ---------------- GEMM 1: Gx = x @ Wx + b  (all gates, all timesteps) ----------------
// C[M=B*N, 768] ; A = x rows (stride T in storage), B = x-part rows (0..255) of Wf/Wi/Wo.
// 64x64 tile, K-chunks of 16, 256 threads, 4x4 micro-tile, f32x2 accumulation.

__global__ __launch_bounds__(256) void gemm_gx(
    const float* __restrict__ X,
    const float* __restrict__ Wf, const float* __restrict__ Wi, const float* __restrict__ Wo,
    const float* __restrict__ bf, const float* __restrict__ bi, const float* __restrict__ bo,
    const int* __restrict__ Np)
{
    const int N = *Np;
    const int m0 = blockIdx.x * 64;
    if (m0 >= B_ * N) return;
    const int j0 = blockIdx.y * 64;         // global gate-col in [0,768)
    const int g  = j0 >> 8;                 // gate id (tile never crosses a gate: 256 % 64 == 0)
    const int d0 = j0 & 255;
    const float* Wg = (g == 0) ? Wf : ((g == 1) ? Wi : Wo);
    const float* bg = (g == 0) ? bf : ((g == 1) ? bi : bo);

    __shared__ float As[64 * 20];   // [m][k], stride 20 (float4-aligned rows)
    __shared__ float Bs[64 * 18];   // [j][k], stride 18 (conflict-free f32x2 reads)

    const int tid = threadIdx.x;
    const int tx = tid & 15, ty = tid >> 4;

    // A-load mapping: row = tid/4, 4 consecutive k
    const int ra = tid >> 2;
    const int ka = (tid & 3) << 2;
    const int mg = m0 + ra;
    const int bb = mg / N, tt = mg % N;
    const float* arow = X + (size_t)(bb * T_ + tt) * DIN;

    // B-load mapping: k = tid/16, 4 consecutive j (transpose into Bs)
    const int kb = tid >> 4;
    const int jb = (tid & 15) << 2;

    float2 acc[4][4];
    #pragma unroll
    for (int i = 0; i < 4; i++)
        #pragma unroll
        for (int jj = 0; jj < 4; jj++) acc[i][jj] = make_float2(0.f, 0.f);

    for (int k0 = 0; k0 < DIN; k0 += 16) {
        float4 av = *reinterpret_cast<const float4*>(arow + k0 + ka);
        *reinterpret_cast<float4*>(&As[ra * 20 + ka]) = av;
        float4 bv = *reinterpret_cast<const float4*>(Wg + (size_t)(k0 + kb) * DC + d0 + jb);
        Bs[(jb + 0) * 18 + kb] = bv.x;
        Bs[(jb + 1) * 18 + kb] = bv.y;
        Bs[(jb + 2) * 18 + kb] = bv.z;
        Bs[(jb + 3) * 18 + kb] = bv.w;
        __syncthreads();
        #pragma unroll
        for (int kp = 0; kp < 8; kp++) {
            float2 a2[4], b2[4];
            #pragma unroll
            for (int i = 0; i < 4; i++)
                a2[i] = *reinterpret_cast<const float2*>(&As[(ty + 16 * i) * 20 + 2 * kp]);
            #pragma unroll
            for (int jj = 0; jj < 4; jj++)
                b2[jj] = *reinterpret_cast<const float2*>(&Bs[(tx + 16 * jj) * 18 + 2 * kp]);
            #pragma unroll
            for (int i = 0; i < 4; i++)
                #pragma unroll
                for (int jj = 0; jj < 4; jj++)
                    acc[i][jj] = ffma2(a2[i], b2[jj], acc[i][jj]);
        }
        __syncthreads();
    }

    #pragma unroll
    for (int i = 0; i < 4; i++) {
        const int m = m0 + ty + 16 * i;
        float* crow = g_Gx + (size_t)m * G3 + j0;
        #pragma unroll
        for (int jj = 0; jj < 4; jj++) {
            const int jc = tx + 16 * jj;
            crow[jc] = acc[i][jj].x + acc[i][jj].y + bg[d0 + jc];
        }
    }
}

// ---------------- Recurrence: persistent, batch-parallel, 4-CTA clusters ----------------
// 32 clusters x 4 CTAs = 128 CTAs. Cluster handles batches {2c, 2c+1}.
// CTA rank r owns cell dims [r*64, r*64+64) for all 3 gates (192 cols of Wh),
// held register-resident: thread (j = tid>>1, ks = tid&1) holds 64 f32x2 of
// Wh[k in ks-half][col j]. Per step: GEMV partials, shfl-reduce pairs, pointwise
// on 128 owner threads, DSMEM-broadcast h_new to the 4 ranks, cluster sync.

__global__ __launch_bounds__(384, 1) __cluster_dims__(4, 1, 1)
void lstm_rec(
    const float* __restrict__ h0, const float* __restrict__ c0,
    const float* __restrict__ Wf, const float* __restrict__ Wi, const float* __restrict__ Wo,
    float* __restrict__ out, const int* __restrict__ Np)
{
    const int N   = *Np;
    const int r   = blockIdx.x & 3;      // cluster rank
    const int cid = blockIdx.x >> 2;     // 0..31
    const int b0  = cid * 2;
    const int tid = threadIdx.x;

    __shared__ float h_s[2][2][256];     // [parity][batch][dim]
    __shared__ float pre_s[2][192];      // [batch][g*64+dd]

    const int j  = tid >> 1;             // 0..191 : local gate-col
    const int ks = tid & 1;              // k-half
    const int g  = j >> 6;
    const int dd = j & 63;
    const int gd = r * 64 + dd;          // column inside the gate matrix
    const float* Wg = (g == 0) ? Wf : ((g == 1) ? Wi : Wo);
    // h-part rows of W: rows 256..511; this thread's k range: [ks*128, ks*128+128)
    const float* wp = Wg + (size_t)(256 + ks * 128) * DC + gd;

    float2 w[64];
    #pragma unroll
    for (int q = 0; q < 64; q++)
        w[q] = make_float2(wp[(size_t)(2 * q) * DC], wp[(size_t)(2 * q + 1) * DC]);

    // init h
    for (int i = tid; i < 512; i += 384) {
        const int b = i >> 8, d = i & 255;
        h_s[0][b][d] = h0[(b0 + b) * DH + d];
    }
    // cell state owners: threads 0..127 -> (pb = tid>>6, pd = tid&63)
    float c_st = 0.f, h_loc = 0.f;
    const int pb = (tid < 128) ? (tid >> 6) : 0;
    const int pd = (tid < 128) ? (tid & 63) : 0;
    if (tid < 128) c_st = c0[(b0 + pb) * DC + r * 64 + pd];
    __syncthreads();

    const int gcol = g * 256 + gd;       // column in Gx layout [f|i|o]
    float gx0 = 0.f, gx1 = 0.f;
    if (ks == 0) {
        gx0 = g_Gx[((size_t)(b0 + 0) * N + 0) * G3 + gcol];
        gx1 = g_Gx[((size_t)(b0 + 1) * N + 0) * G3 + gcol];
    }

    float* out_hf = out + (size_t)B_ * N * DOUT;
    float* out_cf = out_hf + B_ * DH;

    for (int t = 0; t < N; t++) {
        const int p = t & 1;
        const float gxc0 = gx0, gxc1 = gx1;
        const int tn = (t + 1 < N) ? (t + 1) : t;
        if (ks == 0) {   // prefetch next step's Gx
            gx0 = g_Gx[((size_t)(b0 + 0) * N + tn) * G3 + gcol];
            gx1 = g_Gx[((size_t)(b0 + 1) * N + tn) * G3 + gcol];
        }

        #pragma unroll
        for (int b = 0; b < 2; b++) {
            const float2* h2 = reinterpret_cast<const float2*>(&h_s[p][b][ks * 128]);
            float2 accA = make_float2(0.f, 0.f);
            float2 accB = make_float2(0.f, 0.f);
            #pragma unroll
            for (int q = 0; q < 64; q += 2) {
                accA = ffma2(w[q],     h2[q],     accA);
                accB = ffma2(w[q + 1], h2[q + 1], accB);
            }
            float s = accA.x + accA.y + accB.x + accB.y;
            s += __shfl_xor_sync(0xffffffffu, s, 1);   // combine the two k-halves
            if (ks == 0) pre_s[b][j] = s + ((b == 0) ? gxc0 : gxc1);
        }
        __syncthreads();

        if (tid < 128) {
            const float pf = pre_s[pb][pd];
            const float pi = pre_s[pb][64 + pd];
            const float po = pre_s[pb][128 + pd];
            const float f  = sigmoidf_(pf);
            const float ig = sigmoidf_(pi);
            const float z  = tanhf(pi);
            const float o  = sigmoidf_(po);
            c_st  = c_st * f + z * ig;
            h_loc = tanhf(c_st) * o;

            // broadcast h chunk to all 4 cluster CTAs (write-target parity = 1-p)
            const uint32_t laddr = smem_u32(&h_s[1 - p][pb][r * 64 + pd]);
            st_cluster_f32(laddr, 0u, h_loc);
            st_cluster_f32(laddr, 1u, h_loc);
            st_cluster_f32(laddr, 2u, h_loc);
            st_cluster_f32(laddr, 3u, h_loc);

            // stash h_t for the output projection GEMM
            g_H[((size_t)(b0 + pb) * N + t) * DH + r * 64 + pd] = h_loc;
        }
        cluster_sync_();
    }

    if (tid < 128) {
        out_hf[(b0 + pb) * DH + r * 64 + pd] = h_loc;
        out_cf[(b0 + pb) * DC + r * 64 + pd] = c_st;
    }
}

// ---------------- GEMM 3: outs = sigmoid(H @ Wout + bout) ----------------

__global__ __launch_bounds__(256) void gemm_out(
    const float* __restrict__ Wout, const float* __restrict__ bout,
    float* __restrict__ out, const int* __restrict__ Np)
{
    const int N = *Np;
    const int m0 = blockIdx.x * 64;
    if (m0 >= B_ * N) return;
    const int j0 = blockIdx.y * 64;

    __shared__ float As[64 * 20];
    __shared__ float Bs[64 * 18];

    const int tid = threadIdx.x;
    const int tx = tid & 15, ty = tid >> 4;

    const int ra = tid >> 2;
    const int ka = (tid & 3) << 2;
    const float* arow = g_H + (size_t)(m0 + ra) * DH;

    const int kb = tid >> 4;
    const int jb = (tid & 15) << 2;

    float2 acc[4][4];
    #pragma unroll
    for (int i = 0; i < 4; i++)
        #pragma unroll
        for (int jj = 0; jj < 4; jj++) acc[i][jj] = make_float2(0.f, 0.f);

    for (int k0 = 0; k0 < DH; k0 += 16) {
        float4 av = *reinterpret_cast<const float4*>(arow + k0 + ka);
        *reinterpret_cast<float4*>(&As[ra * 20 + ka]) = av;
        float4 bv = *reinterpret_cast<const float4*>(Wout + (size_t)(k0 + kb) * DOUT + j0 + jb);
        Bs[(jb + 0) * 18 + kb] = bv.x;
        Bs[(jb + 1) * 18 + kb] = bv.y;
        Bs[(jb + 2) * 18 + kb] = bv.z;
        Bs[(jb + 3) * 18 + kb] = bv.w;
        __syncthreads();
        #pragma unroll
        for (int kp = 0; kp < 8; kp++) {
            float2 a2[4], b2[4];
            #pragma unroll
            for (int i = 0; i < 4; i++)
                a2[i] = *reinterpret_cast<const float2*>(&As[(ty + 16 * i) * 20 + 2 * kp]);
            #pragma unroll
            for (int jj = 0; jj < 4; jj++)
                b2[jj] = *reinterpret_cast<const float2*>(&Bs[(tx + 16 * jj) * 18 + 2 * kp]);
            #pragma unroll
            for (int i = 0; i < 4; i++)
                #pragma unroll
                for (int jj = 0; jj < 4; jj++)
                    acc[i][jj] = ffma2(a2[i], b2[jj], acc[i][jj]);
        }
        __syncthreads();
    }

    #pragma unroll
    for (int i = 0; i < 4; i++) {
        const int m = m0 + ty + 16 * i;
        float* crow = out + (size_t)m * DOUT + j0;
        #pragma unroll
        for (int jj = 0; jj < 4; jj++) {
            const int jc = tx + 16 * jj;
            crow[jc] = sigmoidf_(acc[i][jj].x + acc[i][jj].y + bout[j0 + jc]);
        }
    }
}

// ---------------- launch ----------------

extern "C" void kernel_launch(void* const* d_in, const int* in_sizes, int n_in,
                              void* d_out, int out_size) {
    const float* x    = (const float*)d_in[0];
    const float* h0   = (const float*)d_in[1];
    const float* c0   = (const float*)d_in[2];
    const float* Wf   = (const float*)d_in[3];
    const float* bfp  = (const float*)d_in[4];
    const float* Wi   = (const float*)d_in[5];
    const float* bip  = (const float*)d_in[6];
    const float* Wo   = (const float*)d_in[7];
    const float* bop  = (const float*)d_in[8];
    const float* Wout = (const float*)d_in[9];
    const float* bout = (const float*)d_in[10];
    const int*   Np   = (const int*)d_in[11];
    float* out = (float*)d_out;

    dim3 g1(B_ * T_ / 64, G3 / 64);
    gemm_gx<<<g1, 256>>>(x, Wf, Wi, Wo, bfp, bip, bop, Np);

    lstm_rec<<<128, 384>>>(h0, c0, Wf, Wi, Wo, out, Np);

    dim3 g3(B_ * T_ / 64, DOUT / 64);
    gemm_out<<<g3, 256>>>(Wout, bout, out, Np);
}

// round 6
// speedup vs baseline: 1.0376x; 1.0376x over previous
#include <cuda_runtime.h>
#include <cstdint>

#define B_    64
#define T_    2048
#define DIN   256
#define DH    256
#define DC    256
#define DOUT  256
#define G3    768   // 3 gates * 256

// Scratch (allocation-free rule: __device__ globals)
__device__ float g_Gx[(size_t)B_ * T_ * G3];  // x-part gate preactivations (+bias)
__device__ float g_H [(size_t)B_ * T_ * DH];  // h_t for all t (for output GEMM)

// ---------------- helpers ----------------

__device__ __forceinline__ float2 ffma2(float2 a, float2 b, float2 c) {
    union U { float2 f; unsigned long long u; };
    U ua, ub, uc, ud;
    ua.f = a; ub.f = b; uc.f = c;
    asm("fma.rn.f32x2 %0, %1, %2, %3;"
        : "=l"(ud.u) : "l"(ua.u), "l"(ub.u), "l"(uc.u));
    return ud.f;
}

__device__ __forceinline__ uint32_t smem_u32(const void* p) {
    uint32_t a;
    asm("{ .reg .u64 t; cvta.to.shared.u64 t, %1; cvt.u32.u64 %0, t; }"
        : "=r"(a) : "l"(p));
    return a;
}

__device__ __forceinline__ void st_cluster_f32(uint32_t laddr, uint32_t rank, float v) {
    asm volatile("{ .reg .b32 ra; mapa.shared::cluster.u32 ra, %0, %1; "
                 "st.shared::cluster.f32 [ra], %2; }"
                 :: "r"(laddr), "r"(rank), "f"(v) : "memory");
}

__device__ __forceinline__ void cluster_sync_() {
    asm volatile("barrier.cluster.arrive.aligned;" ::: "memory");
    asm volatile("barrier.cluster.wait.aligned;" ::: "memory");
}

__device__ __forceinline__ float sigmoidf_(float x) {
    return __fdividef(1.0f, 1.0f + __expf(-x));
}

__device__ __forceinline__ float tanhf_(float x) {
    // tanh(x) = 1 - 2/(exp(2x)+1)  (MUFU-based, ~1e-7 rel in |x|<~10, saturates correctly)
    return 1.0f - __fdividef(2.0f, 1.0f + __expf(2.0f * x));
}

// ================= GEMM core: C[128x64 tile] = A[.,256] @ W[256,.] + b =================
// Smem layout pairs k: As2[kp][m] (float2 over k), Bs2[kp][n]. Inner loop:
// 6 LDS.128 feed 32 FFMA2 per kp. 256 threads, 8x4 f32x2 micro-tile, 2 CTAs/SM.

// ---------------- GEMM 1: Gx = x @ Wx + b (x-part rows 0..255 of Wf/Wi/Wo) ----------------

__global__ __launch_bounds__(256, 2) void gemm_gx(
    const float* __restrict__ X,
    const float* __restrict__ Wf, const float* __restrict__ Wi, const float* __restrict__ Wo,
    const float* __restrict__ bf, const float* __restrict__ bi, const float* __restrict__ bo,
    const int* __restrict__ Np)
{
    const int N = *Np;
    const int m0 = blockIdx.y * 128;
    if (m0 >= B_ * N) return;
    const int j0 = blockIdx.x * 64;         // global gate-col in [0,768)
    const int g  = j0 >> 8;                 // tile never crosses a gate (256 % 64 == 0)
    const int d0 = j0 & 255;
    const float* Wg = (g == 0) ? Wf : ((g == 1) ? Wi : Wo);
    const float* bg = (g == 0) ? bf : ((g == 1) ? bi : bo);

    __shared__ float2 As2[8][128];
    __shared__ float2 Bs2[8][64];

    const int tid = threadIdx.x;
    const int tx = tid & 15, ty = tid >> 4;

    // A-load mapping: row = tid/2, half ha picks k-offset 8*ha (two float4 per thread)
    const int ra = tid >> 1;
    const int ha = tid & 1;
    const int mg = m0 + ra;
    int bb = 0, tt = 0;
    if (mg < B_ * N) { bb = mg / N; tt = mg % N; }
    const float* arow = X + (size_t)(bb * T_ + tt) * DIN + 8 * ha;

    // B-load mapping: k = tid/16, 4 consecutive n
    const int kb = tid >> 4;                // 0..15
    const int nb = (tid & 15) << 2;         // 0..60
    const float* brow = Wg + (size_t)kb * DC + d0 + nb;
    float* bsf = reinterpret_cast<float*>(Bs2);
    float* bsp = bsf + (((kb >> 1) * 64 + nb) << 1) + (kb & 1);

    float2 acc[8][4];
    #pragma unroll
    for (int i = 0; i < 8; i++)
        #pragma unroll
        for (int j = 0; j < 4; j++) acc[i][j] = make_float2(0.f, 0.f);

    for (int k0 = 0; k0 < DIN; k0 += 16) {
        float4 a0 = *reinterpret_cast<const float4*>(arow + k0);
        float4 a1 = *reinterpret_cast<const float4*>(arow + k0 + 4);
        float4 bv = *reinterpret_cast<const float4*>(brow + (size_t)k0 * DC);
        As2[4 * ha + 0][ra] = make_float2(a0.x, a0.y);
        As2[4 * ha + 1][ra] = make_float2(a0.z, a0.w);
        As2[4 * ha + 2][ra] = make_float2(a1.x, a1.y);
        As2[4 * ha + 3][ra] = make_float2(a1.z, a1.w);
        bsp[0] = bv.x; bsp[2] = bv.y; bsp[4] = bv.z; bsp[6] = bv.w;
        __syncthreads();
        #pragma unroll
        for (int kp = 0; kp < 8; kp++) {
            float2 a2[8], b2[4];
            #pragma unroll
            for (int i = 0; i < 4; i++) {
                float4 t = *reinterpret_cast<const float4*>(&As2[kp][32 * i + ty * 2]);
                a2[2 * i]     = make_float2(t.x, t.y);
                a2[2 * i + 1] = make_float2(t.z, t.w);
            }
            float4 t0 = *reinterpret_cast<const float4*>(&Bs2[kp][tx * 2]);
            float4 t1 = *reinterpret_cast<const float4*>(&Bs2[kp][32 + tx * 2]);
            b2[0] = make_float2(t0.x, t0.y); b2[1] = make_float2(t0.z, t0.w);
            b2[2] = make_float2(t1.x, t1.y); b2[3] = make_float2(t1.z, t1.w);
            #pragma unroll
            for (int i = 0; i < 8; i++)
                #pragma unroll
                for (int j = 0; j < 4; j++)
                    acc[i][j] = ffma2(a2[i], b2[j], acc[i][j]);
        }
        __syncthreads();
    }

    const float bg0 = bg[d0 + tx * 2],      bg1 = bg[d0 + tx * 2 + 1];
    const float bg2 = bg[d0 + 32 + tx * 2], bg3 = bg[d0 + 32 + tx * 2 + 1];
    #pragma unroll
    for (int i = 0; i < 8; i++) {
        const int m = m0 + 32 * (i >> 1) + ty * 2 + (i & 1);
        if (m < B_ * N) {
            float* crow = g_Gx + (size_t)m * G3 + j0;
            *reinterpret_cast<float2*>(crow + tx * 2) =
                make_float2(acc[i][0].x + acc[i][0].y + bg0,
                            acc[i][1].x + acc[i][1].y + bg1);
            *reinterpret_cast<float2*>(crow + 32 + tx * 2) =
                make_float2(acc[i][2].x + acc[i][2].y + bg2,
                            acc[i][3].x + acc[i][3].y + bg3);
        }
    }
}

// ---------------- GEMM 3: outs = sigmoid(H @ Wout + bout) ----------------

__global__ __launch_bounds__(256, 2) void gemm_out(
    const float* __restrict__ Wout, const float* __restrict__ bout,
    float* __restrict__ out, const int* __restrict__ Np)
{
    const int N = *Np;
    const int m0 = blockIdx.y * 128;
    if (m0 >= B_ * N) return;
    const int j0 = blockIdx.x * 64;

    __shared__ float2 As2[8][128];
    __shared__ float2 Bs2[8][64];

    const int tid = threadIdx.x;
    const int tx = tid & 15, ty = tid >> 4;

    const int ra = tid >> 1;
    const int ha = tid & 1;
    const int mg = (m0 + ra < B_ * N) ? (m0 + ra) : 0;
    const float* arow = g_H + (size_t)mg * DH + 8 * ha;

    const int kb = tid >> 4;
    const int nb = (tid & 15) << 2;
    const float* brow = Wout + (size_t)kb * DOUT + j0 + nb;
    float* bsf = reinterpret_cast<float*>(Bs2);
    float* bsp = bsf + (((kb >> 1) * 64 + nb) << 1) + (kb & 1);

    float2 acc[8][4];
    #pragma unroll
    for (int i = 0; i < 8; i++)
        #pragma unroll
        for (int j = 0; j < 4; j++) acc[i][j] = make_float2(0.f, 0.f);

    for (int k0 = 0; k0 < DH; k0 += 16) {
        float4 a0 = *reinterpret_cast<const float4*>(arow + k0);
        float4 a1 = *reinterpret_cast<const float4*>(arow + k0 + 4);
        float4 bv = *reinterpret_cast<const float4*>(brow + (size_t)k0 * DOUT);
        As2[4 * ha + 0][ra] = make_float2(a0.x, a0.y);
        As2[4 * ha + 1][ra] = make_float2(a0.z, a0.w);
        As2[4 * ha + 2][ra] = make_float2(a1.x, a1.y);
        As2[4 * ha + 3][ra] = make_float2(a1.z, a1.w);
        bsp[0] = bv.x; bsp[2] = bv.y; bsp[4] = bv.z; bsp[6] = bv.w;
        __syncthreads();
        #pragma unroll
        for (int kp = 0; kp < 8; kp++) {
            float2 a2[8], b2[4];
            #pragma unroll
            for (int i = 0; i < 4; i++) {
                float4 t = *reinterpret_cast<const float4*>(&As2[kp][32 * i + ty * 2]);
                a2[2 * i]     = make_float2(t.x, t.y);
                a2[2 * i + 1] = make_float2(t.z, t.w);
            }
            float4 t0 = *reinterpret_cast<const float4*>(&Bs2[kp][tx * 2]);
            float4 t1 = *reinterpret_cast<const float4*>(&Bs2[kp][32 + tx * 2]);
            b2[0] = make_float2(t0.x, t0.y); b2[1] = make_float2(t0.z, t0.w);
            b2[2] = make_float2(t1.x, t1.y); b2[3] = make_float2(t1.z, t1.w);
            #pragma unroll
            for (int i = 0; i < 8; i++)
                #pragma unroll
                for (int j = 0; j < 4; j++)
                    acc[i][j] = ffma2(a2[i], b2[j], acc[i][j]);
        }
        __syncthreads();
    }

    const float b0v = bout[j0 + tx * 2],      b1v = bout[j0 + tx * 2 + 1];
    const float b2v = bout[j0 + 32 + tx * 2], b3v = bout[j0 + 32 + tx * 2 + 1];
    #pragma unroll
    for (int i = 0; i < 8; i++) {
        const int m = m0 + 32 * (i >> 1) + ty * 2 + (i & 1);
        if (m < B_ * N) {
            float* crow = out + (size_t)m * DOUT + j0;
            *reinterpret_cast<float2*>(crow + tx * 2) =
                make_float2(sigmoidf_(acc[i][0].x + acc[i][0].y + b0v),
                            sigmoidf_(acc[i][1].x + acc[i][1].y + b1v));
            *reinterpret_cast<float2*>(crow + 32 + tx * 2) =
                make_float2(sigmoidf_(acc[i][2].x + acc[i][2].y + b2v),
                            sigmoidf_(acc[i][3].x + acc[i][3].y + b3v));
        }
    }
}

// ---------------- Recurrence: persistent, batch-parallel, 4-CTA clusters ----------------
// 32 clusters x 4 CTAs. Cluster handles batches {2c, 2c+1}. CTA rank r owns cell dims
// [r*64, r*64+64) for all 3 gates (192 Wh columns) register-resident.
// Per step: GEMV (float4 h loads, 1 LDS.128 : 2 FFMA2), shfl pair-reduce, pointwise on
// 128 owner threads, DSMEM h-broadcast, cluster sync.

__global__ __launch_bounds__(384, 1) __cluster_dims__(4, 1, 1)
void lstm_rec(
    const float* __restrict__ h0, const float* __restrict__ c0,
    const float* __restrict__ Wf, const float* __restrict__ Wi, const float* __restrict__ Wo,
    float* __restrict__ out, const int* __restrict__ Np)
{
    const int N   = *Np;
    const int r   = blockIdx.x & 3;      // cluster rank
    const int cid = blockIdx.x >> 2;     // 0..31
    const int b0  = cid * 2;
    const int tid = threadIdx.x;

    __shared__ float h_s[2][2][256];     // [parity][batch][dim]
    __shared__ float pre_s[2][192];      // [batch][g*64+dd]

    const int j  = tid >> 1;             // 0..191 : local gate-col
    const int ks = tid & 1;              // k-half
    const int g  = j >> 6;
    const int dd = j & 63;
    const int gd = r * 64 + dd;          // column inside the gate matrix
    const float* Wg = (g == 0) ? Wf : ((g == 1) ? Wi : Wo);
    // h-part rows of W: rows 256..511; this thread's k range: [ks*128, ks*128+128)
    const float* wp = Wg + (size_t)(256 + ks * 128) * DC + gd;

    float2 w[64];
    #pragma unroll
    for (int q = 0; q < 64; q++)
        w[q] = make_float2(wp[(size_t)(2 * q) * DC], wp[(size_t)(2 * q + 1) * DC]);

    // init h
    for (int i = tid; i < 512; i += 384) {
        const int b = i >> 8, d = i & 255;
        h_s[0][b][d] = h0[(b0 + b) * DH + d];
    }
    // cell-state owners: threads 0..127 -> (pb = tid>>6, pd = tid&63)
    float c_st = 0.f, h_loc = 0.f;
    const int pb = (tid < 128) ? (tid >> 6) : 0;
    const int pd = (tid < 128) ? (tid & 63) : 0;
    if (tid < 128) c_st = c0[(b0 + pb) * DC + r * 64 + pd];
    __syncthreads();

    const int gcol = g * 256 + gd;       // column in Gx layout [f|i|o]
    float gx0 = 0.f, gx1 = 0.f;
    if (ks == 0) {
        gx0 = g_Gx[((size_t)(b0 + 0) * N + 0) * G3 + gcol];
        gx1 = g_Gx[((size_t)(b0 + 1) * N + 0) * G3 + gcol];
    }

    float* out_hf = out + (size_t)B_ * N * DOUT;
    float* out_cf = out_hf + B_ * DH;

    for (int t = 0; t < N; t++) {
        const int p = t & 1;
        const float gxc0 = gx0, gxc1 = gx1;
        const int tn = (t + 1 < N) ? (t + 1) : t;
        if (ks == 0) {   // prefetch next step's Gx
            gx0 = g_Gx[((size_t)(b0 + 0) * N + tn) * G3 + gcol];
            gx1 = g_Gx[((size_t)(b0 + 1) * N + tn) * G3 + gcol];
        }

        #pragma unroll
        for (int b = 0; b < 2; b++) {
            const float4* h4 = reinterpret_cast<const float4*>(&h_s[p][b][ks * 128]);
            float2 accA = make_float2(0.f, 0.f);
            float2 accB = make_float2(0.f, 0.f);
            #pragma unroll
            for (int q = 0; q < 32; q++) {
                float4 hv = h4[q];
                accA = ffma2(w[2 * q],     make_float2(hv.x, hv.y), accA);
                accB = ffma2(w[2 * q + 1], make_float2(hv.z, hv.w), accB);
            }
            float s = accA.x + accA.y + accB.x + accB.y;
            s += __shfl_xor_sync(0xffffffffu, s, 1);   // combine the two k-halves
            if (ks == 0) pre_s[b][j] = s + ((b == 0) ? gxc0 : gxc1);
        }
        __syncthreads();

        if (tid < 128) {
            const float pf = pre_s[pb][pd];
            const float pi = pre_s[pb][64 + pd];
            const float po = pre_s[pb][128 + pd];
            const float f  = sigmoidf_(pf);
            const float ig = sigmoidf_(pi);
            const float z  = tanhf_(pi);
            const float o  = sigmoidf_(po);
            c_st  = c_st * f + z * ig;
            h_loc = tanhf_(c_st) * o;

            // broadcast h chunk to all 4 cluster CTAs (write-target parity = 1-p)
            const uint32_t laddr = smem_u32(&h_s[1 - p][pb][r * 64 + pd]);
            st_cluster_f32(laddr, 0u, h_loc);
            st_cluster_f32(laddr, 1u, h_loc);
            st_cluster_f32(laddr, 2u, h_loc);
            st_cluster_f32(laddr, 3u, h_loc);

            // stash h_t for the output projection GEMM
            g_H[((size_t)(b0 + pb) * N + t) * DH + r * 64 + pd] = h_loc;
        }
        cluster_sync_();
    }

    if (tid < 128) {
        out_hf[(b0 + pb) * DH + r * 64 + pd] = h_loc;
        out_cf[(b0 + pb) * DC + r * 64 + pd] = c_st;
    }
}

// ---------------- launch ----------------

extern "C" void kernel_launch(void* const* d_in, const int* in_sizes, int n_in,
                              void* d_out, int out_size) {
    const float* x    = (const float*)d_in[0];
    const float* h0   = (const float*)d_in[1];
    const float* c0   = (const float*)d_in[2];
    const float* Wf   = (const float*)d_in[3];
    const float* bfp  = (const float*)d_in[4];
    const float* Wi   = (const float*)d_in[5];
    const float* bip  = (const float*)d_in[6];
    const float* Wo   = (const float*)d_in[7];
    const float* bop  = (const float*)d_in[8];
    const float* Wout = (const float*)d_in[9];
    const float* bout = (const float*)d_in[10];
    const int*   Np   = (const int*)d_in[11];
    float* out = (float*)d_out;

    // n-tiles fastest so all 12 column-tiles of an m-tile share A via L2
    dim3 g1(G3 / 64, B_ * T_ / 128);
    gemm_gx<<<g1, 256>>>(x, Wf, Wi, Wo, bfp, bip, bop, Np);

    lstm_rec<<<128, 384>>>(h0, c0, Wf, Wi, Wo, out, Np);

    dim3 g3(DOUT / 64, B_ * T_ / 128);
    gemm_out<<<g3, 256>>>(Wout, bout, out, Np);
}

// round 7
// speedup vs baseline: 1.2889x; 1.2421x over previous
#include <cuda_runtime.h>
#include <cstdint>

#define B_    64
#define T_    2048
#define DIN   256
#define DH    256
#define DC    256
#define DOUT  256
#define G3    768   // 3 gates * 256

// Scratch (allocation-free rule: __device__ globals)
__device__ float g_Gx[(size_t)B_ * T_ * G3];  // x-part gate preactivations (+bias)
__device__ float g_H [(size_t)B_ * T_ * DH];  // h_t for all t (for output GEMM)

// ---------------- helpers ----------------

__device__ __forceinline__ float2 ffma2(float2 a, float2 b, float2 c) {
    union U { float2 f; unsigned long long u; };
    U ua, ub, uc, ud;
    ua.f = a; ub.f = b; uc.f = c;
    asm("fma.rn.f32x2 %0, %1, %2, %3;"
        : "=l"(ud.u) : "l"(ua.u), "l"(ub.u), "l"(uc.u));
    return ud.f;
}

__device__ __forceinline__ uint32_t smem_u32(const void* p) {
    uint32_t a;
    asm("{ .reg .u64 t; cvta.to.shared.u64 t, %1; cvt.u32.u64 %0, t; }"
        : "=r"(a) : "l"(p));
    return a;
}

__device__ __forceinline__ void cluster_sync_() {
    asm volatile("barrier.cluster.arrive.aligned;" ::: "memory");
    asm volatile("barrier.cluster.wait.aligned;" ::: "memory");
}

__device__ __forceinline__ void mbar_init1(uint32_t mbar) {
    asm volatile("mbarrier.init.shared.b64 [%0], %1;" :: "r"(mbar), "r"(1u) : "memory");
}

__device__ __forceinline__ void mbar_expect(uint32_t mbar, uint32_t bytes) {
    asm volatile("mbarrier.arrive.expect_tx.shared.b64 _, [%0], %1;"
                 :: "r"(mbar), "r"(bytes) : "memory");
}

__device__ __forceinline__ void mbar_wait(uint32_t mbar, uint32_t parity) {
    asm volatile(
        "{\n\t"
        ".reg .pred P;\n"
        "W%=:\n\t"
        "mbarrier.try_wait.parity.acquire.cta.shared::cta.b64 P, [%0], %1, 0x989680;\n\t"
        "@P bra.uni D%=;\n\t"
        "bra.uni W%=;\n"
        "D%=:\n\t"
        "}"
        :: "r"(mbar), "r"(parity) : "memory");
}

// store one f32 into rank's smem + count 4 tx bytes on that rank's mbarrier
__device__ __forceinline__ void st_async_remote(uint32_t laddr, uint32_t lmbar,
                                                uint32_t rank, float v) {
    asm volatile(
        "{\n\t"
        ".reg .b32 ra, rb;\n\t"
        "mapa.shared::cluster.u32 ra, %0, %2;\n\t"
        "mapa.shared::cluster.u32 rb, %1, %2;\n\t"
        "st.async.shared::cluster.mbarrier::complete_tx::bytes.b32 [ra], %3, [rb];\n\t"
        "}"
        :: "r"(laddr), "r"(lmbar), "r"(rank), "r"(__float_as_uint(v)) : "memory");
}

__device__ __forceinline__ float sigmoidf_(float x) {
    return __fdividef(1.0f, 1.0f + __expf(-x));
}

__device__ __forceinline__ float tanhf_(float x) {
    return 1.0f - __fdividef(2.0f, 1.0f + __expf(2.0f * x));
}

// ================= GEMM core: 128x128 tile, BK=16, double-buffered =================
// Smem k-pair layout: As2[buf][kp][m], Bs2[buf][kp][n] (float2 over k).
// 256 threads, 8x8 f32x2 micro-tile: per kp 8 LDS.128 feed 64 FFMA2.

// ---------------- GEMM 1: Gx = x @ Wx + b (x-part rows 0..255 of Wf/Wi/Wo) ----------------

__global__ __launch_bounds__(256) void gemm_gx(
    const float* __restrict__ X,
    const float* __restrict__ Wf, const float* __restrict__ Wi, const float* __restrict__ Wo,
    const float* __restrict__ bf, const float* __restrict__ bi, const float* __restrict__ bo,
    const int* __restrict__ Np)
{
    const int N = *Np;
    const int m0 = blockIdx.y * 128;
    if (m0 >= B_ * N) return;
    const int j0v = blockIdx.x * 128;       // 0..640 (tile never crosses a gate)
    const int g  = j0v >> 8;
    const int d0 = j0v & 255;
    const float* Wg = (g == 0) ? Wf : ((g == 1) ? Wi : Wo);
    const float* bg = (g == 0) ? bf : ((g == 1) ? bi : bo);

    __shared__ float2 As2[2][8][128];
    __shared__ float2 Bs2[2][8][128];

    const int tid = threadIdx.x;
    const int tx = tid & 15, ty = tid >> 4;

    // A loader: row = tid/2, half ha -> k-offset 8*ha (two float4)
    const int ra = tid >> 1, ha = tid & 1;
    int mg = m0 + ra; if (mg >= B_ * N) mg = B_ * N - 1;
    const int bb = mg / N, tt = mg % N;
    const float* arow = X + (size_t)(bb * T_ + tt) * DIN + 8 * ha;

    // B loader: kp0 = tid/32 (k-pair row), np0 = tid%32 (n-pair); cols {2np0, 2np0+64}
    const int kp0 = tid >> 5;
    const int np0 = tid & 31;
    const float* bcol = Wg + d0 + 2 * np0;

    float4 a0, a1;
    float2 v00, v01, v10, v11;

    a0 = *reinterpret_cast<const float4*>(arow);
    a1 = *reinterpret_cast<const float4*>(arow + 4);
    v00 = *reinterpret_cast<const float2*>(bcol + (size_t)(2 * kp0) * DC);
    v01 = *reinterpret_cast<const float2*>(bcol + (size_t)(2 * kp0 + 1) * DC);
    v10 = *reinterpret_cast<const float2*>(bcol + (size_t)(2 * kp0) * DC + 64);
    v11 = *reinterpret_cast<const float2*>(bcol + (size_t)(2 * kp0 + 1) * DC + 64);

    As2[0][4 * ha + 0][ra] = make_float2(a0.x, a0.y);
    As2[0][4 * ha + 1][ra] = make_float2(a0.z, a0.w);
    As2[0][4 * ha + 2][ra] = make_float2(a1.x, a1.y);
    As2[0][4 * ha + 3][ra] = make_float2(a1.z, a1.w);
    *reinterpret_cast<float4*>(&Bs2[0][kp0][2 * np0]) =
        make_float4(v00.x, v01.x, v00.y, v01.y);
    *reinterpret_cast<float4*>(&Bs2[0][kp0][2 * np0 + 64]) =
        make_float4(v10.x, v11.x, v10.y, v11.y);
    __syncthreads();

    float2 acc[8][8];
    #pragma unroll
    for (int i = 0; i < 8; i++)
        #pragma unroll
        for (int j = 0; j < 8; j++) acc[i][j] = make_float2(0.f, 0.f);

    #pragma unroll 1
    for (int c = 0; c < 16; ++c) {
        const int buf = c & 1;
        if (c + 1 < 16) {
            const int kk = (c + 1) * 16;
            a0 = *reinterpret_cast<const float4*>(arow + kk);
            a1 = *reinterpret_cast<const float4*>(arow + kk + 4);
            v00 = *reinterpret_cast<const float2*>(bcol + (size_t)(kk + 2 * kp0) * DC);
            v01 = *reinterpret_cast<const float2*>(bcol + (size_t)(kk + 2 * kp0 + 1) * DC);
            v10 = *reinterpret_cast<const float2*>(bcol + (size_t)(kk + 2 * kp0) * DC + 64);
            v11 = *reinterpret_cast<const float2*>(bcol + (size_t)(kk + 2 * kp0 + 1) * DC + 64);
        }
        #pragma unroll
        for (int kp = 0; kp < 8; kp++) {
            float2 a2[8], b2[8];
            #pragma unroll
            for (int i = 0; i < 4; i++) {
                float4 t = *reinterpret_cast<const float4*>(&As2[buf][kp][32 * i + 2 * ty]);
                a2[2 * i]     = make_float2(t.x, t.y);
                a2[2 * i + 1] = make_float2(t.z, t.w);
            }
            #pragma unroll
            for (int j = 0; j < 4; j++) {
                float4 t = *reinterpret_cast<const float4*>(&Bs2[buf][kp][32 * j + 2 * tx]);
                b2[2 * j]     = make_float2(t.x, t.y);
                b2[2 * j + 1] = make_float2(t.z, t.w);
            }
            #pragma unroll
            for (int i = 0; i < 8; i++)
                #pragma unroll
                for (int j = 0; j < 8; j++)
                    acc[i][j] = ffma2(a2[i], b2[j], acc[i][j]);
        }
        if (c + 1 < 16) {
            const int nb = buf ^ 1;
            As2[nb][4 * ha + 0][ra] = make_float2(a0.x, a0.y);
            As2[nb][4 * ha + 1][ra] = make_float2(a0.z, a0.w);
            As2[nb][4 * ha + 2][ra] = make_float2(a1.x, a1.y);
            As2[nb][4 * ha + 3][ra] = make_float2(a1.z, a1.w);
            *reinterpret_cast<float4*>(&Bs2[nb][kp0][2 * np0]) =
                make_float4(v00.x, v01.x, v00.y, v01.y);
            *reinterpret_cast<float4*>(&Bs2[nb][kp0][2 * np0 + 64]) =
                make_float4(v10.x, v11.x, v10.y, v11.y);
        }
        __syncthreads();
    }

    float bgv[8];
    #pragma unroll
    for (int u = 0; u < 4; u++) {
        bgv[2 * u]     = bg[d0 + 32 * u + 2 * tx];
        bgv[2 * u + 1] = bg[d0 + 32 * u + 2 * tx + 1];
    }
    #pragma unroll
    for (int i = 0; i < 8; i++) {
        const int m = m0 + 32 * (i >> 1) + 2 * ty + (i & 1);
        if (m < B_ * N) {
            float* crow = g_Gx + (size_t)m * G3 + j0v;
            #pragma unroll
            for (int u = 0; u < 4; u++)
                *reinterpret_cast<float2*>(crow + 32 * u + 2 * tx) =
                    make_float2(acc[i][2 * u].x + acc[i][2 * u].y + bgv[2 * u],
                                acc[i][2 * u + 1].x + acc[i][2 * u + 1].y + bgv[2 * u + 1]);
        }
    }
}

// ---------------- GEMM 3: outs = sigmoid(H @ Wout + bout) ----------------

__global__ __launch_bounds__(256) void gemm_out(
    const float* __restrict__ Wout, const float* __restrict__ bout,
    float* __restrict__ out, const int* __restrict__ Np)
{
    const int N = *Np;
    const int m0 = blockIdx.y * 128;
    if (m0 >= B_ * N) return;
    const int j0v = blockIdx.x * 128;

    __shared__ float2 As2[2][8][128];
    __shared__ float2 Bs2[2][8][128];

    const int tid = threadIdx.x;
    const int tx = tid & 15, ty = tid >> 4;

    const int ra = tid >> 1, ha = tid & 1;
    int mg = m0 + ra; if (mg >= B_ * N) mg = B_ * N - 1;
    const float* arow = g_H + (size_t)mg * DH + 8 * ha;

    const int kp0 = tid >> 5;
    const int np0 = tid & 31;
    const float* bcol = Wout + j0v + 2 * np0;

    float4 a0, a1;
    float2 v00, v01, v10, v11;

    a0 = *reinterpret_cast<const float4*>(arow);
    a1 = *reinterpret_cast<const float4*>(arow + 4);
    v00 = *reinterpret_cast<const float2*>(bcol + (size_t)(2 * kp0) * DOUT);
    v01 = *reinterpret_cast<const float2*>(bcol + (size_t)(2 * kp0 + 1) * DOUT);
    v10 = *reinterpret_cast<const float2*>(bcol + (size_t)(2 * kp0) * DOUT + 64);
    v11 = *reinterpret_cast<const float2*>(bcol + (size_t)(2 * kp0 + 1) * DOUT + 64);

    As2[0][4 * ha + 0][ra] = make_float2(a0.x, a0.y);
    As2[0][4 * ha + 1][ra] = make_float2(a0.z, a0.w);
    As2[0][4 * ha + 2][ra] = make_float2(a1.x, a1.y);
    As2[0][4 * ha + 3][ra] = make_float2(a1.z, a1.w);
    *reinterpret_cast<float4*>(&Bs2[0][kp0][2 * np0]) =
        make_float4(v00.x, v01.x, v00.y, v01.y);
    *reinterpret_cast<float4*>(&Bs2[0][kp0][2 * np0 + 64]) =
        make_float4(v10.x, v11.x, v10.y, v11.y);
    __syncthreads();

    float2 acc[8][8];
    #pragma unroll
    for (int i = 0; i < 8; i++)
        #pragma unroll
        for (int j = 0; j < 8; j++) acc[i][j] = make_float2(0.f, 0.f);

    #pragma unroll 1
    for (int c = 0; c < 16; ++c) {
        const int buf = c & 1;
        if (c + 1 < 16) {
            const int kk = (c + 1) * 16;
            a0 = *reinterpret_cast<const float4*>(arow + kk);
            a1 = *reinterpret_cast<const float4*>(arow + kk + 4);
            v00 = *reinterpret_cast<const float2*>(bcol + (size_t)(kk + 2 * kp0) * DOUT);
            v01 = *reinterpret_cast<const float2*>(bcol + (size_t)(kk + 2 * kp0 + 1) * DOUT);
            v10 = *reinterpret_cast<const float2*>(bcol + (size_t)(kk + 2 * kp0) * DOUT + 64);
            v11 = *reinterpret_cast<const float2*>(bcol + (size_t)(kk + 2 * kp0 + 1) * DOUT + 64);
        }
        #pragma unroll
        for (int kp = 0; kp < 8; kp++) {
            float2 a2[8], b2[8];
            #pragma unroll
            for (int i = 0; i < 4; i++) {
                float4 t = *reinterpret_cast<const float4*>(&As2[buf][kp][32 * i + 2 * ty]);
                a2[2 * i]     = make_float2(t.x, t.y);
                a2[2 * i + 1] = make_float2(t.z, t.w);
            }
            #pragma unroll
            for (int j = 0; j < 4; j++) {
                float4 t = *reinterpret_cast<const float4*>(&Bs2[buf][kp][32 * j + 2 * tx]);
                b2[2 * j]     = make_float2(t.x, t.y);
                b2[2 * j + 1] = make_float2(t.z, t.w);
            }
            #pragma unroll
            for (int i = 0; i < 8; i++)
                #pragma unroll
                for (int j = 0; j < 8; j++)
                    acc[i][j] = ffma2(a2[i], b2[j], acc[i][j]);
        }
        if (c + 1 < 16) {
            const int nb = buf ^ 1;
            As2[nb][4 * ha + 0][ra] = make_float2(a0.x, a0.y);
            As2[nb][4 * ha + 1][ra] = make_float2(a0.z, a0.w);
            As2[nb][4 * ha + 2][ra] = make_float2(a1.x, a1.y);
            As2[nb][4 * ha + 3][ra] = make_float2(a1.z, a1.w);
            *reinterpret_cast<float4*>(&Bs2[nb][kp0][2 * np0]) =
                make_float4(v00.x, v01.x, v00.y, v01.y);
            *reinterpret_cast<float4*>(&Bs2[nb][kp0][2 * np0 + 64]) =
                make_float4(v10.x, v11.x, v10.y, v11.y);
        }
        __syncthreads();
    }

    float bgv[8];
    #pragma unroll
    for (int u = 0; u < 4; u++) {
        bgv[2 * u]     = bout[j0v + 32 * u + 2 * tx];
        bgv[2 * u + 1] = bout[j0v + 32 * u + 2 * tx + 1];
    }
    #pragma unroll
    for (int i = 0; i < 8; i++) {
        const int m = m0 + 32 * (i >> 1) + 2 * ty + (i & 1);
        if (m < B_ * N) {
            float* crow = out + (size_t)m * DOUT + j0v;
            #pragma unroll
            for (int u = 0; u < 4; u++)
                *reinterpret_cast<float2*>(crow + 32 * u + 2 * tx) =
                    make_float2(
                        sigmoidf_(acc[i][2 * u].x + acc[i][2 * u].y + bgv[2 * u]),
                        sigmoidf_(acc[i][2 * u + 1].x + acc[i][2 * u + 1].y + bgv[2 * u + 1]));
        }
    }
}

// ---------------- Recurrence: persistent, batch-parallel, 4-CTA clusters ----------------
// 32 clusters x 4 CTAs, batches {2c, 2c+1}. Rank r owns cell dims [r*64, r*64+64) for
// all 3 gates, Wh register-resident. Steady-state sync = tx-counted mbarriers fed by
// st.async (data + completion in one message); NO per-step cluster.sync / L1D flush.
// h double-buffered by step parity; 2048B expected tx per CTA per step (2*256 floats).

__global__ __launch_bounds__(384, 1) __cluster_dims__(4, 1, 1)
void lstm_rec(
    const float* __restrict__ h0, const float* __restrict__ c0,
    const float* __restrict__ Wf, const float* __restrict__ Wi, const float* __restrict__ Wo,
    float* __restrict__ out, const int* __restrict__ Np)
{
    const int N   = *Np;
    const int r   = blockIdx.x & 3;
    const int cid = blockIdx.x >> 2;
    const int b0  = cid * 2;
    const int tid = threadIdx.x;

    __shared__ float h_s[2][2][256];     // [parity][batch][dim]
    __shared__ float pre_s[2][192];      // [batch][g*64+dd]
    __shared__ __align__(8) unsigned long long mbar[2];

    const int j  = tid >> 1;             // 0..191 : local gate-col
    const int ks = tid & 1;              // k-half
    const int g  = j >> 6;
    const int dd = j & 63;
    const int gd = r * 64 + dd;
    const float* Wg = (g == 0) ? Wf : ((g == 1) ? Wi : Wo);
    const float* wp = Wg + (size_t)(256 + ks * 128) * DC + gd;

    float2 w[64];
    #pragma unroll
    for (int q = 0; q < 64; q++)
        w[q] = make_float2(wp[(size_t)(2 * q) * DC], wp[(size_t)(2 * q + 1) * DC]);

    const uint32_t mb0 = smem_u32(&mbar[0]);
    const uint32_t mb1 = smem_u32(&mbar[1]);
    if (tid == 0) {
        mbar_init1(mb0);
        mbar_init1(mb1);
        mbar_expect(mb0, 2048);   // first use: h for step 2
        mbar_expect(mb1, 2048);   // first use: h for step 1
    }

    // init h (parity 0) straight from GMEM — every CTA loads its own full copy
    for (int i = tid; i < 512; i += 384) {
        const int b = i >> 8, d = i & 255;
        h_s[0][b][d] = h0[(b0 + b) * DH + d];
    }
    float c_st = 0.f, h_loc = 0.f;
    const int pb = (tid < 128) ? (tid >> 6) : 0;
    const int pd = (tid < 128) ? (tid & 63) : 0;
    if (tid < 128) c_st = c0[(b0 + pb) * DC + r * 64 + pd];
    __syncthreads();
    cluster_sync_();   // all mbarriers initialized before any st.async traffic

    const int gcol = g * 256 + gd;
    float gx0 = 0.f, gx1 = 0.f;
    if (ks == 0) {
        gx0 = g_Gx[((size_t)(b0 + 0) * N + 0) * G3 + gcol];
        gx1 = g_Gx[((size_t)(b0 + 1) * N + 0) * G3 + gcol];
    }

    float* out_hf = out + (size_t)B_ * N * DOUT;
    float* out_cf = out_hf + B_ * DH;

    int ph0 = 0, ph1 = 0;

    for (int t = 0; t < N; t++) {
        const int p = t & 1;

        if (t > 0) {
            const uint32_t mb = p ? mb1 : mb0;
            mbar_wait(mb, (uint32_t)(p ? ph1 : ph0));
            if (p) ph1 ^= 1; else ph0 ^= 1;
            if (tid == 0) mbar_expect(mb, 2048);   // re-arm for use at step t+2
        }

        const float gxc0 = gx0, gxc1 = gx1;
        const int tn = (t + 1 < N) ? (t + 1) : t;
        if (ks == 0) {   // prefetch next step's Gx
            gx0 = g_Gx[((size_t)(b0 + 0) * N + tn) * G3 + gcol];
            gx1 = g_Gx[((size_t)(b0 + 1) * N + tn) * G3 + gcol];
        }

        #pragma unroll
        for (int b = 0; b < 2; b++) {
            const float4* h4 = reinterpret_cast<const float4*>(&h_s[p][b][ks * 128]);
            float2 accA = make_float2(0.f, 0.f);
            float2 accB = make_float2(0.f, 0.f);
            #pragma unroll
            for (int q = 0; q < 32; q++) {
                float4 hv = h4[q];
                accA = ffma2(w[2 * q],     make_float2(hv.x, hv.y), accA);
                accB = ffma2(w[2 * q + 1], make_float2(hv.z, hv.w), accB);
            }
            float s = accA.x + accA.y + accB.x + accB.y;
            s += __shfl_xor_sync(0xffffffffu, s, 1);
            if (ks == 0) pre_s[b][j] = s + ((b == 0) ? gxc0 : gxc1);
        }
        __syncthreads();

        if (tid < 128) {
            const float pf = pre_s[pb][pd];
            const float pi = pre_s[pb][64 + pd];
            const float po = pre_s[pb][128 + pd];
            const float f  = sigmoidf_(pf);
            const float ig = sigmoidf_(pi);
            const float z  = tanhf_(pi);
            const float o  = sigmoidf_(po);
            c_st  = c_st * f + z * ig;
            h_loc = tanhf_(c_st) * o;

            if (t + 1 < N) {
                // push h chunk to all 4 ranks' h_s[1-p] + count tx on their mbar[1-p]
                const uint32_t la = smem_u32(&h_s[1 - p][pb][r * 64 + pd]);
                const uint32_t lb = p ? mb0 : mb1;
                st_async_remote(la, lb, 0u, h_loc);
                st_async_remote(la, lb, 1u, h_loc);
                st_async_remote(la, lb, 2u, h_loc);
                st_async_remote(la, lb, 3u, h_loc);
            }
            g_H[((size_t)(b0 + pb) * N + t) * DH + r * 64 + pd] = h_loc;
        }
    }

    if (tid < 128) {
        out_hf[(b0 + pb) * DH + r * 64 + pd] = h_loc;
        out_cf[(b0 + pb) * DC + r * 64 + pd] = c_st;
    }
    cluster_sync_();   // no CTA exits while peers could still be mid-step
}

// ---------------- launch ----------------

extern "C" void kernel_launch(void* const* d_in, const int* in_sizes, int n_in,
                              void* d_out, int out_size) {
    const float* x    = (const float*)d_in[0];
    const float* h0   = (const float*)d_in[1];
    const float* c0   = (const float*)d_in[2];
    const float* Wf   = (const float*)d_in[3];
    const float* bfp  = (const float*)d_in[4];
    const float* Wi   = (const float*)d_in[5];
    const float* bip  = (const float*)d_in[6];
    const float* Wo   = (const float*)d_in[7];
    const float* bop  = (const float*)d_in[8];
    const float* Wout = (const float*)d_in[9];
    const float* bout = (const float*)d_in[10];
    const int*   Np   = (const int*)d_in[11];
    float* out = (float*)d_out;

    // n-tiles fastest so the column-tiles of an m-tile share A via L2
    dim3 g1(G3 / 128, B_ * T_ / 128);
    gemm_gx<<<g1, 256>>>(x, Wf, Wi, Wo, bfp, bip, bop, Np);

    lstm_rec<<<128, 384>>>(h0, c0, Wf, Wi, Wo, out, Np);

    dim3 g3(DOUT / 128, B_ * T_ / 128);
    gemm_out<<<g3, 256>>>(Wout, bout, out, Np);
}